// round 10
// baseline (speedup 1.0000x reference)
#include <cuda_runtime.h>
#include <cuda_fp16.h>
#include <math.h>
#include <stdint.h>

#define N_NODES 100000
#define N_EDGES 1600000
#define D 64
#define NP 4160              // 64*64+64
#define R3 12480             // 3*NP
#define TOPK 32
#define NBLK 98              // ceil(100000/1024)
#define NCAND (NBLK * TOPK)  // 3136
#define GI_BLOCKS (R3 / 8)   // 1560

// ---------------- scratch (zero-initialized at module load) ----------------
__device__ float g_y[N_NODES];
__device__ unsigned long long g_cand[NCAND];
__device__ __align__(16) float g_zflat[2048];
__device__ float g_gi[R3];
__device__ float g_gh[2][R3];
__device__ __align__(16) float g_neww[NP];
__device__ __align__(128) float  g_xw[(size_t)N_NODES * D];    // layer-0 gather operand (fp32: feeds topk)
__device__ __align__(128) __half g_xwh[(size_t)N_NODES * D];   // layer-1 gather operand (fp16: final out)
__device__ __align__(128) float g_h1[(size_t)N_NODES * D];
__device__ int   g_indeg[N_NODES];
__device__ float g_dinv[N_NODES];
__device__ int   g_rowptr[N_NODES];
__device__ int   g_rowend[N_NODES];
__device__ int   g_cursor[N_NODES];
__device__ int2  g_csre[N_EDGES];
__device__ int   g_total;
__device__ int   g_done;     // gi last-block counter (self-resetting)

__device__ __forceinline__ float wredf(float v) {
    #pragma unroll
    for (int o = 16; o; o >>= 1) v += __shfl_xor_sync(0xffffffffu, v, o);
    return v;
}
__device__ __forceinline__ unsigned fflip(float v) {
    unsigned u = __float_as_uint(v);
    return (u & 0x80000000u) ? ~u : (u | 0x80000000u);
}
__device__ __forceinline__ float funflip(unsigned k) {
    unsigned u = (k & 0x80000000u) ? (k & 0x7fffffffu) : ~k;
    return __uint_as_float(u);
}
__device__ __forceinline__ unsigned long long mkkey(float v, int idx) {
    return ((unsigned long long)fflip(v) << 32) | (unsigned)(~(unsigned)idx);
}

// warp0-only: exact top-32 of sy[n] -> out slots (called with full block, only wid==0 works)
__device__ __forceinline__ void warp_top32(unsigned long long* sy, int n,
                                           unsigned long long* outSlots) {
    int lane = threadIdx.x & 31;
    for (int k = 0; k < TOPK; k++) {
        unsigned long long best = 0ull; int bslot = -1;
        for (int j = lane; j < n; j += 32) {
            unsigned long long kk = sy[j];
            if (kk > best) { best = kk; bslot = j; }
        }
        unsigned long long lb = best;
        #pragma unroll
        for (int o = 16; o; o >>= 1) {
            unsigned long long ok = __shfl_xor_sync(0xffffffffu, best, o);
            if (ok > best) best = ok;
        }
        if (lb == best && bslot >= 0) sy[bslot] = 0ull;   // unique owner removes
        if (lane == 0) outSlots[k] = best;
    }
}

// ---------------- CSR build ----------------
__global__ void k_deg(const int* __restrict__ dst) {
    int e = blockIdx.x * 256 + threadIdx.x;
    if (e < N_EDGES) atomicAdd(&g_indeg[dst[e]], 1);
}

__global__ void k_alloc() {
    __shared__ int ws[32];
    __shared__ int base;
    int t = threadIdx.x;                  // 1024
    int i = blockIdx.x * 1024 + t;
    int lane = t & 31, wid = t >> 5;
    int v = (i < N_NODES) ? g_indeg[i] : 0;
    if (i < N_NODES) g_dinv[i] = rsqrtf((float)(v + 1));
    int x = v;
    #pragma unroll
    for (int o = 1; o < 32; o <<= 1) {
        int y = __shfl_up_sync(0xffffffffu, x, o);
        if (lane >= o) x += y;
    }
    if (lane == 31) ws[wid] = x;
    __syncthreads();
    if (wid == 0) {
        int s = ws[lane];
        #pragma unroll
        for (int o = 1; o < 32; o <<= 1) {
            int y = __shfl_up_sync(0xffffffffu, s, o);
            if (lane >= o) s += y;
        }
        ws[lane] = s;
        if (lane == 31) base = atomicAdd(&g_total, s);
    }
    __syncthreads();
    if (i < N_NODES) {
        int rp = base + ((wid > 0) ? ws[wid - 1] : 0) + x - v;
        g_rowptr[i] = rp;
        g_rowend[i] = rp + v;
        g_cursor[i] = rp;
    }
}

__global__ void k_fill(const int* __restrict__ src, const int* __restrict__ dst) {
    int e = blockIdx.x * 256 + threadIdx.x;
    if (e < N_EDGES) {
        int d = dst[e];
        int s = src[e];
        int pos = atomicAdd(&g_cursor[d], 1);
        g_csre[pos] = make_int2(s, __float_as_int(g_dinv[s]));
    }
}

// ---------------- layer-0: y + per-block exact top-32 ----------------
__global__ void k_y0(const float* __restrict__ x, const float* __restrict__ p) {
    __shared__ __align__(16) float pn[64];
    __shared__ float sp[65];
    __shared__ unsigned long long sy[1024];
    int t = threadIdx.x;   // 1024
    int lane = t & 31, wid = t >> 5;
    if (t < 64) sp[t] = p[t];
    __syncthreads();
    if (t < 32) {
        float v = sp[2 * t] * sp[2 * t] + sp[2 * t + 1] * sp[2 * t + 1];
        v = wredf(v);
        if (t == 0) sp[64] = sqrtf(v) + 1e-8f;
    }
    __syncthreads();
    if (t < 64) pn[t] = sp[t] / sp[64];
    __syncthreads();
    int base = blockIdx.x * 1024;
    float p0 = pn[2 * lane], p1v = pn[2 * lane + 1];
    #pragma unroll 4
    for (int pass = 0; pass < 32; pass++) {
        int slot = pass * 32 + wid;
        int node = base + slot;
        float v = 0.f;
        if (node < N_NODES) {
            float2 hv = ((const float2*)(x + (size_t)node * D))[lane];
            v = hv.x * p0 + hv.y * p1v;
        }
        v = wredf(v);
        if (lane == 0) sy[slot] = (node < N_NODES) ? mkkey(v, node) : 0ull;
    }
    __syncthreads();
    if (wid == 0) warp_top32(sy, 1024, &g_cand[blockIdx.x * TOPK]);
}

// ---------------- layer-1: per-block exact top-32 from g_y ----------------
__global__ void k_part() {
    __shared__ unsigned long long sy[1024];
    int t = threadIdx.x;   // 1024
    int i = blockIdx.x * 1024 + t;
    sy[t] = (i < N_NODES) ? mkkey(g_y[i], i) : 0ull;
    __syncthreads();
    if ((t >> 5) == 0) warp_top32(sy, 1024, &g_cand[blockIdx.x * TOPK]);
}

// ---------------- final: global exact top-32 + zflat ----------------
__global__ void k_sel2(const float* __restrict__ hx, int use_h1) {
    const float* h = use_h1 ? g_h1 : hx;
    __shared__ unsigned long long sc[NCAND];
    __shared__ unsigned long long sel[TOPK];
    __shared__ int selI[TOPK];
    __shared__ float tw[TOPK];
    int t = threadIdx.x;   // 1024
    for (int j = t; j < NCAND; j += 1024) sc[j] = g_cand[j];
    __syncthreads();
    if ((t >> 5) == 0) warp_top32(sc, NCAND, sel);
    __syncthreads();
    if (t < TOPK) {
        unsigned long long kk = sel[t];
        selI[t] = (int)(~(unsigned)(kk & 0xffffffffu));
        tw[t] = tanhf(funflip((unsigned)(kk >> 32)));
    }
    __syncthreads();
    for (int idx = t; idx < 2048; idx += 1024) {
        int k = idx & 31, d = idx >> 5;
        g_zflat[idx] = h[(size_t)selI[k] * D + d] * tw[k];
    }
}

// ---------------- gi mat-vec + fused gate (last block) ----------------
__global__ void k_gi_gate(const float* __restrict__ wih,
                          const float* __restrict__ bih, const float* __restrict__ bhh,
                          const float* __restrict__ w,   const float* __restrict__ b,
                          int layer) {
    __shared__ __align__(16) float zs[2048];
    __shared__ int isLast;
    int t = threadIdx.x;  // 256
    int lane = t & 31, warp = t >> 5;
    for (int j = t; j < 2048; j += 256) zs[j] = g_zflat[j];
    __syncthreads();
    const float4* zs4 = (const float4*)zs;
    int row = blockIdx.x * 8 + warp;
    const float4* r = (const float4*)(wih + (size_t)row * 2048);
    float4 A = make_float4(0.f, 0.f, 0.f, 0.f);
    #pragma unroll 8
    for (int j = lane; j < 512; j += 32) {
        float4 a = __ldcs(r + j), xb = zs4[j];
        A.x += a.x * xb.x; A.y += a.y * xb.y;
        A.z += a.z * xb.z; A.w += a.w * xb.w;
    }
    float v = wredf((A.x + A.y) + (A.z + A.w));
    if (lane == 0) g_gi[row] = v;
    // last-block-done -> gate
    __threadfence();
    __syncthreads();
    if (t == 0) isLast = (atomicAdd(&g_done, 1) == GI_BLOCKS - 1) ? 1 : 0;
    __syncthreads();
    if (isLast) {
        const float* gh = g_gh[layer];
        for (int u = t; u < NP; u += 256) {
            float hv = (u < 4096) ? w[u] : b[u - 4096];
            float ir = g_gi[u] + bih[u],               hr = gh[u] + bhh[u];
            float iz = g_gi[NP + u] + bih[NP + u],     hz = gh[NP + u] + bhh[NP + u];
            float in = g_gi[2*NP + u] + bih[2*NP + u], hn = gh[2*NP + u] + bhh[2*NP + u];
            float rr = 1.f / (1.f + expf(-(ir + hr)));
            float zz = 1.f / (1.f + expf(-(iz + hz)));
            float nn = tanhf(in + rr * hn);
            g_neww[u] = (1.f - zz) * nn + zz * hv;
        }
        __syncthreads();
        if (t == 0) g_done = 0;   // reset for next use
    }
}

// ---------------- gh mat-vec (static inputs; precomputed on side stream) ----------------
__global__ void k_mv_gh(const float* __restrict__ whh, const float* __restrict__ w,
                        const float* __restrict__ b, int layer) {
    __shared__ __align__(16) float hs[NP];
    int t = threadIdx.x;  // 256
    int lane = t & 31, warp = t >> 5;
    for (int j = t; j < 4096; j += 256) hs[j] = w[j];
    if (t < 64) hs[4096 + t] = b[t];
    __syncthreads();
    const float4* hs4 = (const float4*)hs;
    int row = blockIdx.x * 8 + warp;
    const float4* r = (const float4*)(whh + (size_t)row * NP);
    float4 A = make_float4(0.f, 0.f, 0.f, 0.f);
    #pragma unroll 8
    for (int j = lane; j < 1040; j += 32) {
        float4 a = __ldcs(r + j), xb = hs4[j];
        A.x += a.x * xb.x; A.y += a.y * xb.y;
        A.z += a.z * xb.z; A.w += a.w * xb.w;
    }
    float v = wredf((A.x + A.y) + (A.z + A.w));
    if (lane == 0) g_gh[layer][row] = v;
}

// ---------------- xw = h @ W^T (OUT16: fp16 for final layer) ----------------
template<int OUT16>
__global__ void k_xw(const float* __restrict__ hx, int use_h1) {
    const float* h = use_h1 ? g_h1 : hx;
    __shared__ __align__(16) float hsT[64 * 64];
    __shared__ __align__(16) float wsT[64 * 64];
    int t = threadIdx.x;  // 256
    int base = blockIdx.x * 64;
    for (int idx = t; idx < 4096; idx += 256) {
        int n = idx >> 6, d = idx & 63;
        int node = base + n;
        hsT[d * 64 + n] = (node < N_NODES) ? h[(size_t)node * D + d] : 0.f;
    }
    for (int idx = t; idx < 4096; idx += 256) {
        int o = idx >> 6, d = idx & 63;
        wsT[d * 64 + o] = g_neww[idx];
    }
    __syncthreads();
    int tx = t & 15, ty = t >> 4;
    float acc[4][4];
    #pragma unroll
    for (int i = 0; i < 4; i++)
        #pragma unroll
        for (int j = 0; j < 4; j++) acc[i][j] = 0.f;
    #pragma unroll 4
    for (int d = 0; d < 64; d++) {
        float4 a = *(const float4*)&hsT[d * 64 + ty * 4];
        float4 b = *(const float4*)&wsT[d * 64 + tx * 4];
        float av[4] = {a.x, a.y, a.z, a.w};
        float bvv[4] = {b.x, b.y, b.z, b.w};
        #pragma unroll
        for (int i = 0; i < 4; i++)
            #pragma unroll
            for (int j = 0; j < 4; j++) acc[i][j] += av[i] * bvv[j];
    }
    #pragma unroll
    for (int i = 0; i < 4; i++) {
        int node = base + ty * 4 + i;
        if (node < N_NODES) {
            if (OUT16) {
                __half2 h2a = __floats2half2_rn(acc[i][0], acc[i][1]);
                __half2 h2b = __floats2half2_rn(acc[i][2], acc[i][3]);
                ((__half2*)(g_xwh + (size_t)node * D))[tx * 2]     = h2a;
                ((__half2*)(g_xwh + (size_t)node * D))[tx * 2 + 1] = h2b;
            } else {
                ((float4*)(g_xw + (size_t)node * D))[tx] =
                    make_float4(acc[i][0], acc[i][1], acc[i][2], acc[i][3]);
            }
        }
    }
}

// ---------------- GCN aggregation ----------------
// MODE 0: fp32 operand, relu, writes g_h1 + fused y1. MODE 1: fp16 operand, writes out + self-reset.
template<int MODE>
__global__ void k_gat(float* __restrict__ outp, const float* __restrict__ p) {
    __shared__ __align__(16) float pn[64];
    __shared__ float sp[65];
    int t = threadIdx.x;  // 256
    if (MODE == 0) {
        if (t < 64) sp[t] = p[t];
        __syncthreads();
        if (t < 32) {
            float v = sp[2 * t] * sp[2 * t] + sp[2 * t + 1] * sp[2 * t + 1];
            v = wredf(v);
            if (t == 0) sp[64] = sqrtf(v) + 1e-8f;
        }
        __syncthreads();
        if (t < 64) pn[t] = sp[t] / sp[64];
        __syncthreads();
    }
    int i = blockIdx.x * 8 + (t >> 5);
    int lane = t & 31;
    if (i >= N_NODES) return;
    float di = g_dinv[i];
    float2 bb = ((const float2*)(g_neww + 4096))[lane];
    float2 xi, nb = make_float2(0.f, 0.f);
    if (MODE == 0) xi = ((const float2*)(g_xw + (size_t)i * D))[lane];
    else           xi = __half22float2(((const __half2*)(g_xwh + (size_t)i * D))[lane]);
    int s0 = g_rowptr[i], s1 = g_rowend[i];
    #pragma unroll 4
    for (int j = s0; j < s1; j++) {
        int2 e = __ldg(&g_csre[j]);
        float2 v;
        if (MODE == 0) v = ((const float2*)(g_xw + (size_t)e.x * D))[lane];
        else           v = __half22float2(((const __half2*)(g_xwh + (size_t)e.x * D))[lane]);
        float wv = __int_as_float(e.y);
        nb.x += wv * v.x;
        nb.y += wv * v.y;
    }
    float2 acc;
    acc.x = bb.x + di * (di * xi.x + nb.x);
    acc.y = bb.y + di * (di * xi.y + nb.y);
    if (MODE == 0) {
        acc.x = fmaxf(acc.x, 0.f);
        acc.y = fmaxf(acc.y, 0.f);
        ((float2*)(g_h1 + (size_t)i * D))[lane] = acc;
        float v = acc.x * pn[2 * lane] + acc.y * pn[2 * lane + 1];
        v = wredf(v);
        if (lane == 0) g_y[i] = v;
    } else {
        ((float2*)(outp + (size_t)i * D))[lane] = acc;
        if (lane == 0) {
            g_indeg[i] = 0;
            if (i == 0) g_total = 0;
        }
    }
}

// ---------------- stream resources ----------------
struct HxRes {
    cudaStream_t sB = nullptr, sC = nullptr;
    cudaEvent_t evFork = nullptr, evGH0 = nullptr, evGH1 = nullptr, evCSR = nullptr;
    bool ok = false;
    HxRes() {
        ok = (cudaStreamCreateWithFlags(&sB, cudaStreamNonBlocking) == cudaSuccess) &&
             (cudaStreamCreateWithFlags(&sC, cudaStreamNonBlocking) == cudaSuccess) &&
             (cudaEventCreateWithFlags(&evFork, cudaEventDisableTiming) == cudaSuccess) &&
             (cudaEventCreateWithFlags(&evGH0, cudaEventDisableTiming) == cudaSuccess) &&
             (cudaEventCreateWithFlags(&evGH1, cudaEventDisableTiming) == cudaSuccess) &&
             (cudaEventCreateWithFlags(&evCSR, cudaEventDisableTiming) == cudaSuccess);
    }
};
static HxRes hx;

// ---------------- launch ----------------
extern "C" void kernel_launch(void* const* d_in, const int* in_sizes, int n_in,
                              void* d_out, int out_size) {
    const float* x    = (const float*)d_in[0];
    const int*   ei   = (const int*)d_in[1];
    const float* p0   = (const float*)d_in[2];
    const float* p1   = (const float*)d_in[3];
    const float* w0   = (const float*)d_in[4];
    const float* b0   = (const float*)d_in[5];
    const float* w1   = (const float*)d_in[6];
    const float* b1   = (const float*)d_in[7];
    const float* wih0 = (const float*)d_in[8];
    const float* whh0 = (const float*)d_in[9];
    const float* bih0 = (const float*)d_in[10];
    const float* bhh0 = (const float*)d_in[11];
    const float* wih1 = (const float*)d_in[12];
    const float* whh1 = (const float*)d_in[13];
    const float* bih1 = (const float*)d_in[14];
    const float* bhh1 = (const float*)d_in[15];
    float* out = (float*)d_out;

    const int* src = ei;
    const int* dst = ei + N_EDGES;

    bool dual = hx.ok;
    cudaStream_t sA = 0;
    cudaStream_t sB = dual ? hx.sB : sA;
    cudaStream_t sC = dual ? hx.sC : sA;

    if (dual) {
        cudaEventRecord(hx.evFork, sA);
        cudaStreamWaitEvent(sB, hx.evFork, 0);
        cudaStreamWaitEvent(sC, hx.evFork, 0);
    }

    // kernel submissions: #4 (k_sel2) is the profiled launch
    k_mv_gh<<<R3 / 8, 256, 0, sB>>>(whh0, w0, b0, 0);                  // k1
    if (dual) cudaEventRecord(hx.evGH0, sB);
    k_deg<<<(N_EDGES + 255) / 256, 256, 0, sC>>>(dst);                 // k2
    k_y0<<<NBLK, 1024, 0, sA>>>(x, p0);                                // k3
    k_sel2<<<1, 1024, 0, sA>>>(x, 0);                                  // k4 <- profiled

    k_mv_gh<<<R3 / 8, 256, 0, sB>>>(whh1, w1, b1, 1);
    if (dual) cudaEventRecord(hx.evGH1, sB);
    k_alloc<<<(N_NODES + 1023) / 1024, 1024, 0, sC>>>();
    k_fill<<<(N_EDGES + 255) / 256, 256, 0, sC>>>(src, dst);
    if (dual) cudaEventRecord(hx.evCSR, sC);

    // layer 0
    if (dual) cudaStreamWaitEvent(sA, hx.evGH0, 0);
    k_gi_gate<<<GI_BLOCKS, 256, 0, sA>>>(wih0, bih0, bhh0, w0, b0, 0);
    k_xw<0><<<(N_NODES + 63) / 64, 256, 0, sA>>>(x, 0);
    if (dual) cudaStreamWaitEvent(sA, hx.evCSR, 0);
    k_gat<0><<<(N_NODES + 7) / 8, 256, 0, sA>>>(nullptr, p1);

    // layer 1
    k_part<<<NBLK, 1024, 0, sA>>>();
    k_sel2<<<1, 1024, 0, sA>>>(nullptr, 1);
    if (dual) cudaStreamWaitEvent(sA, hx.evGH1, 0);
    k_gi_gate<<<GI_BLOCKS, 256, 0, sA>>>(wih1, bih1, bhh1, w1, b1, 1);
    k_xw<1><<<(N_NODES + 63) / 64, 256, 0, sA>>>(nullptr, 1);
    k_gat<1><<<(N_NODES + 7) / 8, 256, 0, sA>>>(out, nullptr);
}

// round 11
// speedup vs baseline: 1.0727x; 1.0727x over previous
#include <cuda_runtime.h>
#include <cuda_fp16.h>
#include <math.h>
#include <stdint.h>

#define N_NODES 100000
#define N_EDGES 1600000
#define D 64
#define NP 4160              // 64*64+64
#define R3 12480             // 3*NP
#define TOPK 32
#define NBLK 98              // ceil(100000/1024)
#define NCAND (NBLK * TOPK)  // 3136
#define GI_BLOCKS (R3 / 8)   // 1560

// ---------------- scratch (zero-initialized at module load) ----------------
__device__ float g_y[N_NODES];
__device__ unsigned long long g_cand[NCAND];
__device__ __align__(16) float g_zflat[2048];
__device__ float g_gi[R3];
__device__ float g_gh[2][R3];
__device__ __align__(16) float g_neww[NP];
__device__ __align__(128) float  g_xw[(size_t)N_NODES * D];    // layer-0 gather operand (fp32: feeds topk)
__device__ __align__(128) __half g_xwh[(size_t)N_NODES * D];   // layer-1 gather operand (fp16: final out)
__device__ __align__(128) float g_h1[(size_t)N_NODES * D];
__device__ int   g_indeg[N_NODES];
__device__ float g_dinv[N_NODES];
__device__ int   g_rowptr[N_NODES];
__device__ int   g_rowend[N_NODES];
__device__ int   g_cursor[N_NODES];
__device__ int2  g_csre[N_EDGES];
__device__ int   g_total;
__device__ int   g_done;     // gi last-block counter (self-resetting)

__device__ __forceinline__ float wredf(float v) {
    #pragma unroll
    for (int o = 16; o; o >>= 1) v += __shfl_xor_sync(0xffffffffu, v, o);
    return v;
}
__device__ __forceinline__ unsigned fflip(float v) {
    unsigned u = __float_as_uint(v);
    return (u & 0x80000000u) ? ~u : (u | 0x80000000u);
}
__device__ __forceinline__ float funflip(unsigned k) {
    unsigned u = (k & 0x80000000u) ? (k & 0x7fffffffu) : ~k;
    return __uint_as_float(u);
}
__device__ __forceinline__ unsigned long long mkkey(float v, int idx) {
    return ((unsigned long long)fflip(v) << 32) | (unsigned)(~(unsigned)idx);
}
__device__ __forceinline__ unsigned long long wmaxull(unsigned long long b) {
    #pragma unroll
    for (int o = 16; o; o >>= 1) {
        unsigned long long ok = __shfl_xor_sync(0xffffffffu, b, o);
        if (ok > b) b = ok;
    }
    return b;
}

// Block-parallel exact top-32. Each thread holds MAXC candidate keys in registers.
// wb: smem[33] scratch (wb[0..31] warp bests, wb[32] winner). outSel: smem/global [TOPK].
// 2 barriers per round. Keys must be unique (index embedded); 0 = empty.
template<int MAXC>
__device__ __forceinline__ void block_top32(unsigned long long (&kk)[MAXC],
                                            unsigned long long* wb,
                                            unsigned long long* outSel) {
    int t = threadIdx.x, lane = t & 31, wid = t >> 5;
    int nw = blockDim.x >> 5;
    for (int k = 0; k < TOPK; k++) {
        unsigned long long best = 0ull;
        #pragma unroll
        for (int c = 0; c < MAXC; c++) if (kk[c] > best) best = kk[c];
        best = wmaxull(best);
        if (lane == 0) wb[wid] = best;
        __syncthreads();
        if (wid == 0) {
            unsigned long long b2 = (lane < nw) ? wb[lane] : 0ull;
            b2 = wmaxull(b2);
            if (lane == 0) { wb[32] = b2; outSel[k] = b2; }
        }
        __syncthreads();
        unsigned long long win = wb[32];
        #pragma unroll
        for (int c = 0; c < MAXC; c++) if (kk[c] == win) kk[c] = 0ull;
    }
}

// ---------------- CSR build ----------------
__global__ void k_deg(const int* __restrict__ dst) {
    int e = blockIdx.x * 256 + threadIdx.x;
    if (e < N_EDGES) atomicAdd(&g_indeg[dst[e]], 1);
}

__global__ void k_alloc() {
    __shared__ int ws[32];
    __shared__ int base;
    int t = threadIdx.x;                  // 1024
    int i = blockIdx.x * 1024 + t;
    int lane = t & 31, wid = t >> 5;
    int v = (i < N_NODES) ? g_indeg[i] : 0;
    if (i < N_NODES) g_dinv[i] = rsqrtf((float)(v + 1));
    int x = v;
    #pragma unroll
    for (int o = 1; o < 32; o <<= 1) {
        int y = __shfl_up_sync(0xffffffffu, x, o);
        if (lane >= o) x += y;
    }
    if (lane == 31) ws[wid] = x;
    __syncthreads();
    if (wid == 0) {
        int s = ws[lane];
        #pragma unroll
        for (int o = 1; o < 32; o <<= 1) {
            int y = __shfl_up_sync(0xffffffffu, s, o);
            if (lane >= o) s += y;
        }
        ws[lane] = s;
        if (lane == 31) base = atomicAdd(&g_total, s);
    }
    __syncthreads();
    if (i < N_NODES) {
        int rp = base + ((wid > 0) ? ws[wid - 1] : 0) + x - v;
        g_rowptr[i] = rp;
        g_rowend[i] = rp + v;
        g_cursor[i] = rp;
    }
}

__global__ void k_fill(const int* __restrict__ src, const int* __restrict__ dst) {
    int e = blockIdx.x * 256 + threadIdx.x;
    if (e < N_EDGES) {
        int d = dst[e];
        int s = src[e];
        int pos = atomicAdd(&g_cursor[d], 1);
        g_csre[pos] = make_int2(s, __float_as_int(g_dinv[s]));
    }
}

// ---------------- layer-0: y + per-block exact top-32 (block-parallel) ----------------
__global__ void k_y0(const float* __restrict__ x, const float* __restrict__ p) {
    __shared__ __align__(16) float pn[64];
    __shared__ float sp[65];
    __shared__ unsigned long long sy[1024];
    __shared__ unsigned long long wb[33];
    int t = threadIdx.x;   // 1024
    int lane = t & 31, wid = t >> 5;
    if (t < 64) sp[t] = p[t];
    __syncthreads();
    if (t < 32) {
        float v = sp[2 * t] * sp[2 * t] + sp[2 * t + 1] * sp[2 * t + 1];
        v = wredf(v);
        if (t == 0) sp[64] = sqrtf(v) + 1e-8f;
    }
    __syncthreads();
    if (t < 64) pn[t] = sp[t] / sp[64];
    __syncthreads();
    int base = blockIdx.x * 1024;
    float p0 = pn[2 * lane], p1v = pn[2 * lane + 1];
    #pragma unroll 4
    for (int pass = 0; pass < 32; pass++) {
        int slot = pass * 32 + wid;
        int node = base + slot;
        float v = 0.f;
        if (node < N_NODES) {
            float2 hv = ((const float2*)(x + (size_t)node * D))[lane];
            v = hv.x * p0 + hv.y * p1v;
        }
        v = wredf(v);
        if (lane == 0) sy[slot] = (node < N_NODES) ? mkkey(v, node) : 0ull;
    }
    __syncthreads();
    unsigned long long kk[1];
    kk[0] = sy[t];
    block_top32<1>(kk, wb, &g_cand[blockIdx.x * TOPK]);
}

// ---------------- layer-1: per-block exact top-32 from g_y ----------------
__global__ void k_part() {
    __shared__ unsigned long long wb[33];
    int t = threadIdx.x;   // 1024
    int i = blockIdx.x * 1024 + t;
    unsigned long long kk[1];
    kk[0] = (i < N_NODES) ? mkkey(g_y[i], i) : 0ull;
    block_top32<1>(kk, wb, &g_cand[blockIdx.x * TOPK]);
}

// ---------------- final: global exact top-32 + zflat (block-parallel) ----------------
__global__ void k_sel2(const float* __restrict__ hx, int use_h1) {
    const float* h = use_h1 ? g_h1 : hx;
    __shared__ unsigned long long sel[TOPK];
    __shared__ unsigned long long wb[33];
    __shared__ int selI[TOPK];
    __shared__ float tw[TOPK];
    int t = threadIdx.x;   // 1024
    unsigned long long kk[4];
    #pragma unroll
    for (int c = 0; c < 4; c++) {
        int j = c * 1024 + t;
        kk[c] = (j < NCAND) ? g_cand[j] : 0ull;
    }
    block_top32<4>(kk, wb, sel);
    __syncthreads();
    if (t < TOPK) {
        unsigned long long s = sel[t];
        selI[t] = (int)(~(unsigned)(s & 0xffffffffu));
        tw[t] = tanhf(funflip((unsigned)(s >> 32)));
    }
    __syncthreads();
    for (int idx = t; idx < 2048; idx += 1024) {
        int k = idx & 31, d = idx >> 5;
        g_zflat[idx] = h[(size_t)selI[k] * D + d] * tw[k];
    }
}

// ---------------- gi mat-vec + fused gate (last block) ----------------
__global__ void k_gi_gate(const float* __restrict__ wih,
                          const float* __restrict__ bih, const float* __restrict__ bhh,
                          const float* __restrict__ w,   const float* __restrict__ b,
                          int layer) {
    __shared__ __align__(16) float zs[2048];
    __shared__ int isLast;
    int t = threadIdx.x;  // 256
    int lane = t & 31, warp = t >> 5;
    for (int j = t; j < 2048; j += 256) zs[j] = g_zflat[j];
    __syncthreads();
    const float4* zs4 = (const float4*)zs;
    int row = blockIdx.x * 8 + warp;
    const float4* r = (const float4*)(wih + (size_t)row * 2048);
    float4 A = make_float4(0.f, 0.f, 0.f, 0.f);
    #pragma unroll 8
    for (int j = lane; j < 512; j += 32) {
        float4 a = __ldcs(r + j), xb = zs4[j];
        A.x += a.x * xb.x; A.y += a.y * xb.y;
        A.z += a.z * xb.z; A.w += a.w * xb.w;
    }
    float v = wredf((A.x + A.y) + (A.z + A.w));
    if (lane == 0) g_gi[row] = v;
    __threadfence();
    __syncthreads();
    if (t == 0) isLast = (atomicAdd(&g_done, 1) == GI_BLOCKS - 1) ? 1 : 0;
    __syncthreads();
    if (isLast) {
        const float* gh = g_gh[layer];
        for (int u = t; u < NP; u += 256) {
            float hv = (u < 4096) ? w[u] : b[u - 4096];
            float ir = g_gi[u] + bih[u],               hr = gh[u] + bhh[u];
            float iz = g_gi[NP + u] + bih[NP + u],     hz = gh[NP + u] + bhh[NP + u];
            float in = g_gi[2*NP + u] + bih[2*NP + u], hn = gh[2*NP + u] + bhh[2*NP + u];
            float rr = 1.f / (1.f + expf(-(ir + hr)));
            float zz = 1.f / (1.f + expf(-(iz + hz)));
            float nn = tanhf(in + rr * hn);
            g_neww[u] = (1.f - zz) * nn + zz * hv;
        }
        __syncthreads();
        if (t == 0) g_done = 0;
    }
}

// ---------------- gh mat-vec (static inputs; precomputed on side stream) ----------------
__global__ void k_mv_gh(const float* __restrict__ whh, const float* __restrict__ w,
                        const float* __restrict__ b, int layer) {
    __shared__ __align__(16) float hs[NP];
    int t = threadIdx.x;  // 256
    int lane = t & 31, warp = t >> 5;
    for (int j = t; j < 4096; j += 256) hs[j] = w[j];
    if (t < 64) hs[4096 + t] = b[t];
    __syncthreads();
    const float4* hs4 = (const float4*)hs;
    int row = blockIdx.x * 8 + warp;
    const float4* r = (const float4*)(whh + (size_t)row * NP);
    float4 A = make_float4(0.f, 0.f, 0.f, 0.f);
    #pragma unroll 8
    for (int j = lane; j < 1040; j += 32) {
        float4 a = __ldcs(r + j), xb = hs4[j];
        A.x += a.x * xb.x; A.y += a.y * xb.y;
        A.z += a.z * xb.z; A.w += a.w * xb.w;
    }
    float v = wredf((A.x + A.y) + (A.z + A.w));
    if (lane == 0) g_gh[layer][row] = v;
}

// ---------------- xw = h @ W^T (OUT16: fp16 for final layer) ----------------
template<int OUT16>
__global__ void k_xw(const float* __restrict__ hx, int use_h1) {
    const float* h = use_h1 ? g_h1 : hx;
    __shared__ __align__(16) float hsT[64 * 64];
    __shared__ __align__(16) float wsT[64 * 64];
    int t = threadIdx.x;  // 256
    int base = blockIdx.x * 64;
    for (int idx = t; idx < 4096; idx += 256) {
        int n = idx >> 6, d = idx & 63;
        int node = base + n;
        hsT[d * 64 + n] = (node < N_NODES) ? h[(size_t)node * D + d] : 0.f;
    }
    for (int idx = t; idx < 4096; idx += 256) {
        int o = idx >> 6, d = idx & 63;
        wsT[d * 64 + o] = g_neww[idx];
    }
    __syncthreads();
    int tx = t & 15, ty = t >> 4;
    float acc[4][4];
    #pragma unroll
    for (int i = 0; i < 4; i++)
        #pragma unroll
        for (int j = 0; j < 4; j++) acc[i][j] = 0.f;
    #pragma unroll 4
    for (int d = 0; d < 64; d++) {
        float4 a = *(const float4*)&hsT[d * 64 + ty * 4];
        float4 b = *(const float4*)&wsT[d * 64 + tx * 4];
        float av[4] = {a.x, a.y, a.z, a.w};
        float bvv[4] = {b.x, b.y, b.z, b.w};
        #pragma unroll
        for (int i = 0; i < 4; i++)
            #pragma unroll
            for (int j = 0; j < 4; j++) acc[i][j] += av[i] * bvv[j];
    }
    #pragma unroll
    for (int i = 0; i < 4; i++) {
        int node = base + ty * 4 + i;
        if (node < N_NODES) {
            if (OUT16) {
                __half2 h2a = __floats2half2_rn(acc[i][0], acc[i][1]);
                __half2 h2b = __floats2half2_rn(acc[i][2], acc[i][3]);
                ((__half2*)(g_xwh + (size_t)node * D))[tx * 2]     = h2a;
                ((__half2*)(g_xwh + (size_t)node * D))[tx * 2 + 1] = h2b;
            } else {
                ((float4*)(g_xw + (size_t)node * D))[tx] =
                    make_float4(acc[i][0], acc[i][1], acc[i][2], acc[i][3]);
            }
        }
    }
}

// ---------------- GCN aggregation ----------------
template<int MODE>
__global__ void k_gat(float* __restrict__ outp, const float* __restrict__ p) {
    __shared__ __align__(16) float pn[64];
    __shared__ float sp[65];
    int t = threadIdx.x;  // 256
    if (MODE == 0) {
        if (t < 64) sp[t] = p[t];
        __syncthreads();
        if (t < 32) {
            float v = sp[2 * t] * sp[2 * t] + sp[2 * t + 1] * sp[2 * t + 1];
            v = wredf(v);
            if (t == 0) sp[64] = sqrtf(v) + 1e-8f;
        }
        __syncthreads();
        if (t < 64) pn[t] = sp[t] / sp[64];
        __syncthreads();
    }
    int i = blockIdx.x * 8 + (t >> 5);
    int lane = t & 31;
    if (i >= N_NODES) return;
    float di = g_dinv[i];
    float2 bb = ((const float2*)(g_neww + 4096))[lane];
    float2 xi, nb = make_float2(0.f, 0.f);
    if (MODE == 0) xi = ((const float2*)(g_xw + (size_t)i * D))[lane];
    else           xi = __half22float2(((const __half2*)(g_xwh + (size_t)i * D))[lane]);
    int s0 = g_rowptr[i], s1 = g_rowend[i];
    #pragma unroll 4
    for (int j = s0; j < s1; j++) {
        int2 e = __ldg(&g_csre[j]);
        float2 v;
        if (MODE == 0) v = ((const float2*)(g_xw + (size_t)e.x * D))[lane];
        else           v = __half22float2(((const __half2*)(g_xwh + (size_t)e.x * D))[lane]);
        float wv = __int_as_float(e.y);
        nb.x += wv * v.x;
        nb.y += wv * v.y;
    }
    float2 acc;
    acc.x = bb.x + di * (di * xi.x + nb.x);
    acc.y = bb.y + di * (di * xi.y + nb.y);
    if (MODE == 0) {
        acc.x = fmaxf(acc.x, 0.f);
        acc.y = fmaxf(acc.y, 0.f);
        ((float2*)(g_h1 + (size_t)i * D))[lane] = acc;
        float v = acc.x * pn[2 * lane] + acc.y * pn[2 * lane + 1];
        v = wredf(v);
        if (lane == 0) g_y[i] = v;
    } else {
        ((float2*)(outp + (size_t)i * D))[lane] = acc;
        if (lane == 0) {
            g_indeg[i] = 0;
            if (i == 0) g_total = 0;
        }
    }
}

// ---------------- stream resources ----------------
struct HxRes {
    cudaStream_t sB = nullptr, sC = nullptr;
    cudaEvent_t evFork = nullptr, evGH0 = nullptr, evGH1 = nullptr, evCSR = nullptr;
    bool ok = false;
    HxRes() {
        ok = (cudaStreamCreateWithFlags(&sB, cudaStreamNonBlocking) == cudaSuccess) &&
             (cudaStreamCreateWithFlags(&sC, cudaStreamNonBlocking) == cudaSuccess) &&
             (cudaEventCreateWithFlags(&evFork, cudaEventDisableTiming) == cudaSuccess) &&
             (cudaEventCreateWithFlags(&evGH0, cudaEventDisableTiming) == cudaSuccess) &&
             (cudaEventCreateWithFlags(&evGH1, cudaEventDisableTiming) == cudaSuccess) &&
             (cudaEventCreateWithFlags(&evCSR, cudaEventDisableTiming) == cudaSuccess);
    }
};
static HxRes hx;

// ---------------- launch ----------------
extern "C" void kernel_launch(void* const* d_in, const int* in_sizes, int n_in,
                              void* d_out, int out_size) {
    const float* x    = (const float*)d_in[0];
    const int*   ei   = (const int*)d_in[1];
    const float* p0   = (const float*)d_in[2];
    const float* p1   = (const float*)d_in[3];
    const float* w0   = (const float*)d_in[4];
    const float* b0   = (const float*)d_in[5];
    const float* w1   = (const float*)d_in[6];
    const float* b1   = (const float*)d_in[7];
    const float* wih0 = (const float*)d_in[8];
    const float* whh0 = (const float*)d_in[9];
    const float* bih0 = (const float*)d_in[10];
    const float* bhh0 = (const float*)d_in[11];
    const float* wih1 = (const float*)d_in[12];
    const float* whh1 = (const float*)d_in[13];
    const float* bih1 = (const float*)d_in[14];
    const float* bhh1 = (const float*)d_in[15];
    float* out = (float*)d_out;

    const int* src = ei;
    const int* dst = ei + N_EDGES;

    bool dual = hx.ok;
    cudaStream_t sA = 0;
    cudaStream_t sB = dual ? hx.sB : sA;
    cudaStream_t sC = dual ? hx.sC : sA;

    if (dual) {
        cudaEventRecord(hx.evFork, sA);
        cudaStreamWaitEvent(sB, hx.evFork, 0);
        cudaStreamWaitEvent(sC, hx.evFork, 0);
    }

    // submission #4 = k_sel2 (profiled): verify the block-parallel fix
    k_mv_gh<<<R3 / 8, 256, 0, sB>>>(whh0, w0, b0, 0);                  // k1
    if (dual) cudaEventRecord(hx.evGH0, sB);
    k_deg<<<(N_EDGES + 255) / 256, 256, 0, sC>>>(dst);                 // k2
    k_y0<<<NBLK, 1024, 0, sA>>>(x, p0);                                // k3
    k_sel2<<<1, 1024, 0, sA>>>(x, 0);                                  // k4 <- profiled

    k_mv_gh<<<R3 / 8, 256, 0, sB>>>(whh1, w1, b1, 1);
    if (dual) cudaEventRecord(hx.evGH1, sB);
    k_alloc<<<(N_NODES + 1023) / 1024, 1024, 0, sC>>>();
    k_fill<<<(N_EDGES + 255) / 256, 256, 0, sC>>>(src, dst);
    if (dual) cudaEventRecord(hx.evCSR, sC);

    // layer 0
    if (dual) cudaStreamWaitEvent(sA, hx.evGH0, 0);
    k_gi_gate<<<GI_BLOCKS, 256, 0, sA>>>(wih0, bih0, bhh0, w0, b0, 0);
    k_xw<0><<<(N_NODES + 63) / 64, 256, 0, sA>>>(x, 0);
    if (dual) cudaStreamWaitEvent(sA, hx.evCSR, 0);
    k_gat<0><<<(N_NODES + 7) / 8, 256, 0, sA>>>(nullptr, p1);

    // layer 1
    k_part<<<NBLK, 1024, 0, sA>>>();
    k_sel2<<<1, 1024, 0, sA>>>(nullptr, 1);
    if (dual) cudaStreamWaitEvent(sA, hx.evGH1, 0);
    k_gi_gate<<<GI_BLOCKS, 256, 0, sA>>>(wih1, bih1, bhh1, w1, b1, 1);
    k_xw<1><<<(N_NODES + 63) / 64, 256, 0, sA>>>(nullptr, 1);
    k_gat<1><<<(N_NODES + 7) / 8, 256, 0, sA>>>(out, nullptr);
}